// round 1
// baseline (speedup 1.0000x reference)
#include <cuda_runtime.h>

// SpatialShift: x (ns=128, m=12, t=784, c=64) fp32.
// ns = b*16 + h*4 + w (H=W=4, shift s=1). Channel d = m*64 + c, fold f=48.
//   d in [0,  48): out(h,w) = x(h+1,w)   else 0
//   d in [48, 96): out(h,w) = x(h-1,w)   else 0
//   d in [96,144): out(h,w) = x(h,w+1)   else 0
//   d in [144,192): out(h,w) = x(h,w-1)  else 0
//   d in [192,240): out(h,w) = x(h-1,w-1) else identity
//   d in [240,288): out(h,w) = x(h+1,w+1) else identity
//   d in [288,336): out(h,w) = x(h-1,w+1) else identity
//   d in [336,384): out(h,w) = x(h+1,w-1) else identity
//   d >= 384      : identity
// Pure ns-index permutation => fully coalesced float4 copy.

// Packed delta tables: 2 bits per group g (0..8), value = delta + 1.
// dh: {+1,-1,0,0,-1,+1,-1,+1, 0} -> {2,0,1,1,0,2,0,2,1} -> 0x18862 | (1<<16)
// dw: { 0, 0,+1,-1,-1,+1,+1,-1, 0} -> {1,1,2,0,0,2,2,0,1}
#define DH_PACK 100434u  // 34898 + (1<<16)
#define DW_PACK 75813u   // 10277 + (1<<16)

__global__ void __launch_bounds__(256, 8)
spatial_shift_kernel(const float4* __restrict__ x, float4* __restrict__ out) {
    const int c4      = threadIdx.x & 15;   // float4 index within c (0..15)
    const int t_local = threadIdx.x >> 4;   // 0..15

    int blk = blockIdx.x;
    const int tchunk = blk % 49;  blk /= 49;   // 49 * 16 = 784 = t
    const int m      = blk % 12;  blk /= 12;
    const int ns     = blk;                    // 0..127

    const int t = tchunk * 16 + t_local;
    const int h = (ns >> 2) & 3;
    const int w = ns & 3;

    const int d = m * 64 + c4 * 4;
    int g = d / 48;
    if (g > 8) g = 8;

    const int dh = (int)((DH_PACK >> (2 * g)) & 3u) - 1;
    const int dw = (int)((DW_PACK >> (2 * g)) & 3u) - 1;

    int hs = h + dh;
    int ws = w + dw;
    bool zero = false;
    if (((unsigned)hs > 3u) || ((unsigned)ws > 3u)) {
        if (g < 4) {
            zero = true;            // axis shifts: out-of-bounds -> 0
        } else {
            hs = h; ws = w;         // diagonal shifts: border -> identity
        }
    }

    const long out_idx = (((long)(ns * 12 + m)) * 784 + t) * 16 + c4;

    float4 v = make_float4(0.f, 0.f, 0.f, 0.f);
    if (!zero) {
        const int ns_src = (ns & ~15) | (hs << 2) | ws;
        const long src_idx = (((long)(ns_src * 12 + m)) * 784 + t) * 16 + c4;
        v = x[src_idx];
    }
    out[out_idx] = v;
}

extern "C" void kernel_launch(void* const* d_in, const int* in_sizes, int n_in,
                              void* d_out, int out_size) {
    const float4* x = (const float4*)d_in[0];
    float4* out = (float4*)d_out;
    // total float4s = 128*12*784*64/4 = 19,267,584 ; blocks = /256 = 75,264
    spatial_shift_kernel<<<75264, 256>>>(x, out);
}

// round 2
// speedup vs baseline: 1.0503x; 1.0503x over previous
#include <cuda_runtime.h>

// SpatialShift: x (ns=128, m=12, t=784, c=64) fp32.
// ns = b*16 + h*4 + w (H=W=4, shift s=1). Channel d = m*64 + c, fold f=48.
// Pure ns-index permutation => fully coalesced float4 streaming copy.
//
// R2: 7 float4 per thread (MLP=7, loads front-batched), streaming cache
// hints (__ldcs/__stcs), index math amortized 7x.

// Packed delta tables: 2 bits per group g (0..8), value = delta + 1.
// dh: {+1,-1,0,0,-1,+1,-1,+1, 0}
// dw: { 0, 0,+1,-1,-1,+1,+1,-1, 0}
#define DH_PACK 100434u
#define DW_PACK 75813u

__global__ void __launch_bounds__(256)
spatial_shift_kernel(const float4* __restrict__ x, float4* __restrict__ out) {
    const int c4      = threadIdx.x & 15;   // float4 index within c (0..15)
    const int t_local = threadIdx.x >> 4;   // 0..15

    int blk = blockIdx.x;
    const int tchunk = blk % 7;   blk /= 7;    // 7 * 112 = 784 = t
    const int m      = blk % 12;  blk /= 12;
    const int ns     = blk;                    // 0..127

    const int h = (ns >> 2) & 3;
    const int w = ns & 3;

    const int d = m * 64 + c4 * 4;
    int g = d / 48;
    if (g > 8) g = 8;

    const int dh = (int)((DH_PACK >> (2 * g)) & 3u) - 1;
    const int dw = (int)((DW_PACK >> (2 * g)) & 3u) - 1;

    int hs = h + dh;
    int ws = w + dw;
    bool zero = false;
    if (((unsigned)hs > 3u) || ((unsigned)ws > 3u)) {
        if (g < 4) {
            zero = true;            // axis shifts: out-of-bounds -> 0
        } else {
            hs = h; ws = w;         // diagonal shifts: border -> identity
        }
    }

    const int t0 = tchunk * 112 + t_local;
    // index of float4 for (ns, m, t, c4): ((ns*12 + m)*784 + t)*16 + c4
    const long base_out = (((long)(ns * 12 + m)) * 784 + t0) * 16 + c4;

    float4 v[7];
#pragma unroll
    for (int i = 0; i < 7; i++) v[i] = make_float4(0.f, 0.f, 0.f, 0.f);

    if (!zero) {
        const int ns_src = (ns & ~15) | (hs << 2) | ws;
        const long base_src = (((long)(ns_src * 12 + m)) * 784 + t0) * 16 + c4;
#pragma unroll
        for (int i = 0; i < 7; i++)
            v[i] = __ldcs(&x[base_src + (long)i * 256]);   // +16 t each = 256 float4
    }

#pragma unroll
    for (int i = 0; i < 7; i++)
        __stcs(&out[base_out + (long)i * 256], v[i]);
}

extern "C" void kernel_launch(void* const* d_in, const int* in_sizes, int n_in,
                              void* d_out, int out_size) {
    const float4* x = (const float4*)d_in[0];
    float4* out = (float4*)d_out;
    // blocks = 128 * 12 * 7 = 10,752 ; each moves 256 threads * 7 float4
    spatial_shift_kernel<<<10752, 256>>>(x, out);
}